// round 9
// baseline (speedup 1.0000x reference)
#include <cuda_runtime.h>
#include <math.h>
#include <stdint.h>

// Problem constants
#define NIMG   48            // 16 batches * 3 channels
#define NN     1024
#define OUT_HW 224
#define NTAPS  10
#define NBATCH 16
#define HCOLS  513           // Hermitian-unique columns (0..512)
#define HSTR   528           // padded row stride (float2) for pass-1 output
#define FSTR   1058          // padded per-FFT smem region stride (float2); 2116 words % 32 == 4

// ---------------- scratch (device globals; no allocations allowed) ----------
__device__ float2 d_scratch1[(size_t)NIMG * NN * NN];  // pass-1 output [img][row][k<=512] (HSTR stride)
__device__ float2 d_scratch2[(size_t)NIMG * NN * NN];  // spec as float [img][sc][sr]
__device__ float  d_tmpA[(size_t)NIMG * NN * OUT_HW];  // resize pass-A output [img][sc][oy]
__device__ float2 d_tw[1024];                          // exp(-2*pi*i*k/1024)
__device__ float  d_wt[OUT_HW * NTAPS];
__device__ int    d_j0[OUT_HW];
__device__ unsigned int d_gmin[NBATCH];
__device__ unsigned int d_gmax[NBATCH];

// ---------------- complex helpers -------------------------------------------
__device__ __forceinline__ float2 cadd(float2 a, float2 b){ return make_float2(a.x+b.x, a.y+b.y); }
__device__ __forceinline__ float2 csub(float2 a, float2 b){ return make_float2(a.x-b.x, a.y-b.y); }
__device__ __forceinline__ float2 cmul(float2 a, float2 b){
    return make_float2(fmaf(a.x, b.x, -a.y*b.y), fmaf(a.x, b.y, a.y*b.x));
}

#define SIDX(i) ((i) + ((i) >> 5))

// ---------------- 16-point DIF FFT in registers (natural-order output) ------
__device__ __forceinline__ void fft16(float2 x[16]){
    float2 y[16];
    #pragma unroll
    for (int n = 0; n < 4; ++n){
        float2 a = x[n], b = x[n+4], c = x[n+8], d = x[n+12];
        float2 t0 = cadd(a,c), t1 = csub(a,c), t2 = cadd(b,d), t3 = csub(b,d);
        float2 mit3 = make_float2(t3.y, -t3.x);       // -i*(b-d)
        y[n]      = cadd(t0, t2);                     // r=0
        y[4+n]    = cadd(t1, mit3);                   // r=1
        y[8+n]    = csub(t0, t2);                     // r=2
        y[12+n]   = csub(t1, mit3);                   // r=3
    }
    const float C1 = 0.92387953251128674f, S1 = 0.38268343236508978f;
    const float C2 = 0.70710678118654757f;
    // twiddle W16^{n*r} on y[4r+n]
    y[5]  = cmul(y[5],  make_float2( C1, -S1));   // W^1
    y[6]  = cmul(y[6],  make_float2( C2, -C2));   // W^2
    y[7]  = cmul(y[7],  make_float2( S1, -C1));   // W^3
    y[9]  = cmul(y[9],  make_float2( C2, -C2));   // W^2
    y[10] = make_float2(y[10].y, -y[10].x);       // W^4 = -i
    y[11] = cmul(y[11], make_float2(-C2, -C2));   // W^6
    y[13] = cmul(y[13], make_float2( S1, -C1));   // W^3
    y[14] = cmul(y[14], make_float2(-C2, -C2));   // W^6
    y[15] = cmul(y[15], make_float2(-C1,  S1));   // W^9 = -W^1
    #pragma unroll
    for (int r = 0; r < 4; ++r){
        float2 a = y[4*r], b = y[4*r+1], c = y[4*r+2], d = y[4*r+3];
        float2 t0 = cadd(a,c), t1 = csub(a,c), t2 = cadd(b,d), t3 = csub(b,d);
        float2 mit3 = make_float2(t3.y, -t3.x);
        x[r]    = cadd(t0, t2);
        x[r+4]  = cadd(t1, mit3);
        x[r+8]  = csub(t0, t2);
        x[r+12] = csub(t1, mit3);
    }
}

// ---------------- 1024-pt FFT: 64 threads, 16 elems/thread ------------------
// Pre: v[q] = x[t + 64q]. s = this FFT's padded smem region (>= FSTR float2),
// safe to overwrite on entry for all block threads.
// Post: v[m] = X[(t>>2) + 16*m + 256*kk], kk = bit-swap of (t&3) {0,2,1,3}.
// Contains 2 block-wide __syncthreads (all groups in the block run in lockstep).
__device__ __forceinline__ void fft1024_64t(float2* s, int t, float2 v[16]){
    fft16(v);
    {   // twiddle W1024^{t*m}
        float2 w = d_tw[t]; float2 tw = w;
        #pragma unroll
        for (int m = 1; m < 16; ++m){ v[m] = cmul(v[m], tw); tw = cmul(tw, w); }
    }
    #pragma unroll
    for (int m = 0; m < 16; ++m) s[SIDX(m*64 + t)] = v[m];
    __syncthreads();
    const int r = t >> 2, n0 = t & 3;
    #pragma unroll
    for (int j = 0; j < 16; ++j) v[j] = s[SIDX(r*64 + n0 + 4*j)];
    __syncthreads();   // region free for reuse after this
    fft16(v);
    {   // twiddle W64^{n0*r2}
        float2 w = d_tw[16*n0]; float2 tw = w;
        #pragma unroll
        for (int m = 1; m < 16; ++m){ v[m] = cmul(v[m], tw); tw = cmul(tw, w); }
    }
    // final radix-4 across lanes (groups of 4) via shfl
    #pragma unroll
    for (int m = 0; m < 16; ++m){
        float2 z = v[m];
        float2 p = make_float2(__shfl_xor_sync(0xffffffffu, z.x, 2),
                               __shfl_xor_sync(0xffffffffu, z.y, 2));
        float2 a = (n0 & 2) ? csub(p, z) : cadd(z, p);
        if (n0 == 3) a = make_float2(a.y, -a.x);      // * -i
        float2 q = make_float2(__shfl_xor_sync(0xffffffffu, a.x, 1),
                               __shfl_xor_sync(0xffffffffu, a.y, 1));
        v[m] = (n0 & 1) ? csub(q, a) : cadd(a, q);
    }
}
__device__ __forceinline__ int kkmap(int n0){ return ((n0 & 1) << 1) | (n0 >> 1); }

// ---------------- init ------------------------------------------------------
__global__ void init_kernel(){
    int t = blockIdx.x * blockDim.x + threadIdx.x;
    if (t < 1024){
        double ang = -2.0 * M_PI * (double)t / 1024.0;
        d_tw[t] = make_float2((float)cos(ang), (float)sin(ang));
    }
    int o = t - 1024;
    if (o >= 0 && o < OUT_HW){
        const double inv_scale = 1024.0 / 224.0;
        const double ks = inv_scale;
        double c = ((double)o + 0.5) * inv_scale - 0.5;
        int j0 = (int)ceil(c - ks);
        if (j0 < 0) j0 = 0;
        double w[NTAPS]; double sum = 0.0;
        #pragma unroll
        for (int k = 0; k < NTAPS; ++k){
            int j = j0 + k;
            double ww = 0.0;
            if (j <= 1023){
                double x = fabs((double)j - c) / ks;
                ww = (x < 1.0) ? (1.0 - x) : 0.0;
            }
            w[k] = ww; sum += ww;
        }
        #pragma unroll
        for (int k = 0; k < NTAPS; ++k) d_wt[o*NTAPS + k] = (float)(w[k] / sum);
        d_j0[o] = j0;
    }
    int mi = t - (1024 + OUT_HW);
    if (mi >= 0 && mi < NBATCH){
        d_gmin[mi] = 0x7F800000u;
        d_gmax[mi] = 0u;
    }
}

// ---------------- pass 1: paired-row real FFT (4 pairs / block) -------------
__global__ void __launch_bounds__(256) fft_rows_pair(const float* __restrict__ x){
    __shared__ float2 s[4 * FSTR];
    const int gl = threadIdx.x >> 6;         // FFT group within block
    const int t  = threadIdx.x & 63;
    const int img  = blockIdx.x >> 7;
    const int quad = blockIdx.x & 127;
    const int pr   = quad * 4 + gl;          // row pair index 0..511
    const float* x1 = x + ((size_t)img * NN + 2*pr) * NN;
    const float* x2 = x1 + NN;
    float2* sg = s + gl * FSTR;

    float2 v[16];
    #pragma unroll
    for (int q = 0; q < 16; ++q){
        int n = t + 64*q;
        v[q] = make_float2(x1[n], x2[n]);
    }
    fft1024_64t(sg, t, v);

    // write natural order into smem for the Hermitian pair split
    const int r = t >> 2, n0 = t & 3;
    const int kbase = r + 256 * kkmap(n0);
    #pragma unroll
    for (int m = 0; m < 16; ++m) sg[SIDX(kbase + 16*m)] = v[m];
    __syncthreads();

    float2* o1 = d_scratch1 + ((size_t)img * NN + 2*pr) * HSTR;
    float2* o2 = o1 + HSTR;
    for (int k = t; k <= 512; k += 64){
        float2 Zk = sg[SIDX(k)];
        float2 Zm = sg[SIDX((1024 - k) & 1023)];
        o1[k] = make_float2(0.5f*(Zk.x + Zm.x), 0.5f*(Zk.y - Zm.y));
        o2[k] = make_float2(0.5f*(Zk.y + Zm.y), 0.5f*(Zm.x - Zk.x));
    }
}

// ---------------- pass 2: fused gather + column FFT + log-mag + shift + mirror
// Block: 4 columns (one img), 256 threads. Tile-loads pass-1 output coalesced,
// runs 4 column FFTs, writes spec (and Hermitian mirror) + min/max.
__global__ void __launch_bounds__(256) fft_cols_fused(){
    __shared__ float2 s[4 * FSTR];
    __shared__ float smin[8], smax[8];
    const int bid  = blockIdx.x;
    const int img  = bid / 129;
    const int tile = bid - img * 129;
    const int c0   = tile * 4;
    const int cnt  = (HCOLS - c0 < 4) ? (HCOLS - c0) : 4;

    const float2* I = d_scratch1 + (size_t)img * NN * HSTR;
    // tile load: 4 cols x 1024 rows, coalesced 32B sectors per row
    for (int idx = threadIdx.x; idx < 4096; idx += 256){
        int cl = idx & 3, row = idx >> 2;
        if (cl < cnt)
            s[cl * FSTR + SIDX(row)] = I[(size_t)row * HSTR + c0 + cl];
    }
    __syncthreads();

    const int gl = threadIdx.x >> 6;
    const int t  = threadIdx.x & 63;
    float2* sg = s + gl * FSTR;
    float2 v[16];
    #pragma unroll
    for (int q = 0; q < 16; ++q) v[q] = sg[SIDX(t + 64*q)];
    __syncthreads();                     // everyone read their inputs before core overwrites
    fft1024_64t(sg, t, v);

    const bool valid = (gl < cnt);
    const int c   = c0 + gl;
    const int sc  = (c + 512) & 1023;
    const int sc2 = (1536 - c) & 1023;
    const int r = t >> 2, n0 = t & 3;
    const int kbase = r + 256 * kkmap(n0);
    float* spB = (float*)d_scratch2 + ((size_t)img << 20);

    float lmin = 3.4e38f, lmax = 0.f;
    if (valid){
        #pragma unroll
        for (int m = 0; m < 16; ++m){
            int rr  = kbase + 16*m;
            int sr  = (rr + 512) & 1023;
            int sr2 = (1536 - rr) & 1023;
            float m2 = fmaf(v[m].x, v[m].x, v[m].y * v[m].y);
            float val = log1pf(sqrtf(m2));
            spB[(size_t)sc  * NN + sr ] = val;
            spB[(size_t)sc2 * NN + sr2] = val;
            lmin = fminf(lmin, val);
            lmax = fmaxf(lmax, val);
        }
    }
    #pragma unroll
    for (int off = 16; off; off >>= 1){
        lmin = fminf(lmin, __shfl_xor_sync(0xFFFFFFFFu, lmin, off));
        lmax = fmaxf(lmax, __shfl_xor_sync(0xFFFFFFFFu, lmax, off));
    }
    const int wid = threadIdx.x >> 5, lane = threadIdx.x & 31;
    if (lane == 0){ smin[wid] = lmin; smax[wid] = lmax; }
    __syncthreads();
    if (threadIdx.x == 0){
        #pragma unroll
        for (int i = 1; i < 8; ++i){ lmin = fminf(lmin, smin[i]); lmax = fmaxf(lmax, smax[i]); }
        int b = img / 3;
        atomicMin(&d_gmin[b], __float_as_uint(lmin));
        atomicMax(&d_gmax[b], __float_as_uint(lmax));
    }
}

// ---------------- pass 3a: resize along sr (contiguous) -> oy ----------------
__global__ void __launch_bounds__(224) resize_passA(){
    __shared__ float sh[NN];
    const int bid = blockIdx.x;
    const int img = bid >> 10;
    const int sc  = bid & 1023;
    const float* S = (const float*)d_scratch2 + ((size_t)img << 20) + (size_t)sc * NN;
    for (int i = threadIdx.x; i < NN; i += 224) sh[i] = S[i];
    __syncthreads();
    const int oy = threadIdx.x;
    const int j0 = d_j0[oy];
    float acc = 0.f;
    #pragma unroll
    for (int k = 0; k < NTAPS; ++k)
        acc = fmaf(d_wt[oy*NTAPS + k], sh[min(j0 + k, 1023)], acc);
    d_tmpA[((size_t)img * NN + sc) * OUT_HW + oy] = acc;
}

// ---------------- pass 3b: resize along sc -> ox, + normalize ---------------
__global__ void __launch_bounds__(224) resize_passB(float* __restrict__ out){
    const int bid = blockIdx.x;
    const int img = bid / OUT_HW;
    const int ox  = bid % OUT_HW;
    const int oy  = threadIdx.x;
    const int j0  = d_j0[ox];
    float acc = 0.f;
    #pragma unroll
    for (int k = 0; k < NTAPS; ++k){
        int j = min(j0 + k, 1023);
        acc = fmaf(d_wt[ox*NTAPS + k], d_tmpA[((size_t)img * NN + j) * OUT_HW + oy], acc);
    }
    const int b = img / 3;
    const float mn = __uint_as_float(d_gmin[b]);
    const float mx = __uint_as_float(d_gmax[b]);
    const float inv = 1.f / (mx - mn + 1e-8f);
    out[((size_t)img * OUT_HW + oy) * OUT_HW + ox] = (acc - mn) * inv;
}

// ---------------- launch -----------------------------------------------------
extern "C" void kernel_launch(void* const* d_in, const int* in_sizes, int n_in,
                              void* d_out, int out_size){
    (void)in_sizes; (void)n_in; (void)out_size;
    const float* images = (const float*)d_in[0];
    float* out = (float*)d_out;

    init_kernel<<<6, 256>>>();
    fft_rows_pair<<<NIMG * 128, 256>>>(images);
    fft_cols_fused<<<NIMG * 129, 256>>>();
    resize_passA<<<NIMG * NN, 224>>>();
    resize_passB<<<NIMG * OUT_HW, 224>>>(out);
}

// round 10
// speedup vs baseline: 1.4633x; 1.4633x over previous
#include <cuda_runtime.h>
#include <math.h>
#include <stdint.h>

// Problem constants
#define NIMG   48            // 16 batches * 3 channels
#define NN     1024
#define OUT_HW 224
#define NTAPS  10
#define NBATCH 16
#define HCOLS  513           // Hermitian-unique columns (0..512)
#define HSTR   528           // padded row stride (float2) for pass-1 output
#define FSTR   1058          // padded per-FFT smem region stride (float2)

// ---------------- scratch (device globals; no allocations allowed) ----------
__device__ float2 d_scratch1[(size_t)NIMG * NN * HSTR];  // pass-1 output [img][row][k<=512]
__device__ float  d_tmpA[(size_t)NIMG * NN * OUT_HW];    // sr-resized spec [img][sc][oy]
__device__ float2 d_tw[1024];                            // exp(-2*pi*i*k/1024)
__device__ float  d_wt[OUT_HW * NTAPS];
__device__ int    d_j0[OUT_HW];
__device__ unsigned int d_gmin[NBATCH];
__device__ unsigned int d_gmax[NBATCH];

// ---------------- complex helpers -------------------------------------------
__device__ __forceinline__ float2 cadd(float2 a, float2 b){ return make_float2(a.x+b.x, a.y+b.y); }
__device__ __forceinline__ float2 csub(float2 a, float2 b){ return make_float2(a.x-b.x, a.y-b.y); }
__device__ __forceinline__ float2 cmul(float2 a, float2 b){
    return make_float2(fmaf(a.x, b.x, -a.y*b.y), fmaf(a.x, b.y, a.y*b.x));
}

#define SIDX(i) ((i) + ((i) >> 5))

// ---------------- 16-point DIF FFT in registers (natural-order output) ------
__device__ __forceinline__ void fft16(float2 x[16]){
    float2 y[16];
    #pragma unroll
    for (int n = 0; n < 4; ++n){
        float2 a = x[n], b = x[n+4], c = x[n+8], d = x[n+12];
        float2 t0 = cadd(a,c), t1 = csub(a,c), t2 = cadd(b,d), t3 = csub(b,d);
        float2 mit3 = make_float2(t3.y, -t3.x);       // -i*(b-d)
        y[n]      = cadd(t0, t2);
        y[4+n]    = cadd(t1, mit3);
        y[8+n]    = csub(t0, t2);
        y[12+n]   = csub(t1, mit3);
    }
    const float C1 = 0.92387953251128674f, S1 = 0.38268343236508978f;
    const float C2 = 0.70710678118654757f;
    y[5]  = cmul(y[5],  make_float2( C1, -S1));
    y[6]  = cmul(y[6],  make_float2( C2, -C2));
    y[7]  = cmul(y[7],  make_float2( S1, -C1));
    y[9]  = cmul(y[9],  make_float2( C2, -C2));
    y[10] = make_float2(y[10].y, -y[10].x);
    y[11] = cmul(y[11], make_float2(-C2, -C2));
    y[13] = cmul(y[13], make_float2( S1, -C1));
    y[14] = cmul(y[14], make_float2(-C2, -C2));
    y[15] = cmul(y[15], make_float2(-C1,  S1));
    #pragma unroll
    for (int r = 0; r < 4; ++r){
        float2 a = y[4*r], b = y[4*r+1], c = y[4*r+2], d = y[4*r+3];
        float2 t0 = cadd(a,c), t1 = csub(a,c), t2 = cadd(b,d), t3 = csub(b,d);
        float2 mit3 = make_float2(t3.y, -t3.x);
        x[r]    = cadd(t0, t2);
        x[r+4]  = cadd(t1, mit3);
        x[r+8]  = csub(t0, t2);
        x[r+12] = csub(t1, mit3);
    }
}

// ---------------- 1024-pt FFT: 64 threads, 16 elems/thread ------------------
// Pre: v[q] = x[t + 64q]. Post: v[m] = X[(t>>2) + 16*m + 256*kk], kk = kkmap(t&3).
// Two block-wide __syncthreads inside; s region is free for reuse after return.
__device__ __forceinline__ void fft1024_64t(float2* s, int t, float2 v[16]){
    fft16(v);
    {
        float2 w = d_tw[t]; float2 tw = w;
        #pragma unroll
        for (int m = 1; m < 16; ++m){ v[m] = cmul(v[m], tw); tw = cmul(tw, w); }
    }
    #pragma unroll
    for (int m = 0; m < 16; ++m) s[SIDX(m*64 + t)] = v[m];
    __syncthreads();
    const int r = t >> 2, n0 = t & 3;
    #pragma unroll
    for (int j = 0; j < 16; ++j) v[j] = s[SIDX(r*64 + n0 + 4*j)];
    __syncthreads();
    fft16(v);
    {
        float2 w = d_tw[16*n0]; float2 tw = w;
        #pragma unroll
        for (int m = 1; m < 16; ++m){ v[m] = cmul(v[m], tw); tw = cmul(tw, w); }
    }
    #pragma unroll
    for (int m = 0; m < 16; ++m){
        float2 z = v[m];
        float2 p = make_float2(__shfl_xor_sync(0xffffffffu, z.x, 2),
                               __shfl_xor_sync(0xffffffffu, z.y, 2));
        float2 a = (n0 & 2) ? csub(p, z) : cadd(z, p);
        if (n0 == 3) a = make_float2(a.y, -a.x);
        float2 q = make_float2(__shfl_xor_sync(0xffffffffu, a.x, 1),
                               __shfl_xor_sync(0xffffffffu, a.y, 1));
        v[m] = (n0 & 1) ? csub(q, a) : cadd(a, q);
    }
}
__device__ __forceinline__ int kkmap(int n0){ return ((n0 & 1) << 1) | (n0 >> 1); }

// ---------------- init ------------------------------------------------------
__global__ void init_kernel(){
    int t = blockIdx.x * blockDim.x + threadIdx.x;
    if (t < 1024){
        double ang = -2.0 * M_PI * (double)t / 1024.0;
        d_tw[t] = make_float2((float)cos(ang), (float)sin(ang));
    }
    int o = t - 1024;
    if (o >= 0 && o < OUT_HW){
        const double inv_scale = 1024.0 / 224.0;
        const double ks = inv_scale;
        double c = ((double)o + 0.5) * inv_scale - 0.5;
        int j0 = (int)ceil(c - ks);
        if (j0 < 0) j0 = 0;
        double w[NTAPS]; double sum = 0.0;
        #pragma unroll
        for (int k = 0; k < NTAPS; ++k){
            int j = j0 + k;
            double ww = 0.0;
            if (j <= 1023){
                double x = fabs((double)j - c) / ks;
                ww = (x < 1.0) ? (1.0 - x) : 0.0;
            }
            w[k] = ww; sum += ww;
        }
        #pragma unroll
        for (int k = 0; k < NTAPS; ++k) d_wt[o*NTAPS + k] = (float)(w[k] / sum);
        d_j0[o] = j0;
    }
    int mi = t - (1024 + OUT_HW);
    if (mi >= 0 && mi < NBATCH){
        d_gmin[mi] = 0x7F800000u;
        d_gmax[mi] = 0u;
    }
}

// ---------------- pass 1: paired-row real FFT (4 pairs / block) -------------
__global__ void __launch_bounds__(256) fft_rows_pair(const float* __restrict__ x){
    __shared__ float2 s[4 * FSTR];
    const int gl = threadIdx.x >> 6;
    const int t  = threadIdx.x & 63;
    const int img  = blockIdx.x >> 7;
    const int quad = blockIdx.x & 127;
    const int pr   = quad * 4 + gl;
    const float* x1 = x + ((size_t)img * NN + 2*pr) * NN;
    const float* x2 = x1 + NN;
    float2* sg = s + gl * FSTR;

    float2 v[16];
    #pragma unroll
    for (int q = 0; q < 16; ++q){
        int n = t + 64*q;
        v[q] = make_float2(x1[n], x2[n]);
    }
    fft1024_64t(sg, t, v);

    const int r = t >> 2, n0 = t & 3;
    const int kbase = r + 256 * kkmap(n0);
    #pragma unroll
    for (int m = 0; m < 16; ++m) sg[SIDX(kbase + 16*m)] = v[m];
    __syncthreads();

    float2* o1 = d_scratch1 + ((size_t)img * NN + 2*pr) * HSTR;
    float2* o2 = o1 + HSTR;
    for (int k = t; k <= 512; k += 64){
        float2 Zk = sg[SIDX(k)];
        float2 Zm = sg[SIDX((1024 - k) & 1023)];
        o1[k] = make_float2(0.5f*(Zk.x + Zm.x), 0.5f*(Zk.y - Zm.y));
        o2[k] = make_float2(0.5f*(Zk.y + Zm.y), 0.5f*(Zm.x - Zk.x));
    }
}

// ---------------- pass 2: fused column FFT + log-mag + min/max + sr-resize --
// Block: 4 Hermitian-unique columns of one image. After the FFT, the block's
// smem is reused as 4 float arrays (spec column indexed by shifted row sr);
// both the column and its Hermitian mirror (index flip) are resized along sr
// and written straight to d_tmpA. The full spectrum never touches DRAM.
__global__ void __launch_bounds__(256) fft_cols_fused(){
    __shared__ float2 s[4 * FSTR];
    __shared__ float smin[8], smax[8];
    const int bid  = blockIdx.x;
    const int img  = bid / 129;
    const int tile = bid - img * 129;
    const int c0   = tile * 4;
    const int cnt  = (HCOLS - c0 < 4) ? (HCOLS - c0) : 4;

    const float2* I = d_scratch1 + (size_t)img * NN * HSTR;
    for (int idx = threadIdx.x; idx < 4096; idx += 256){
        int cl = idx & 3, row = idx >> 2;
        if (cl < cnt)
            s[cl * FSTR + SIDX(row)] = I[(size_t)row * HSTR + c0 + cl];
    }
    __syncthreads();

    const int gl = threadIdx.x >> 6;
    const int t  = threadIdx.x & 63;
    float2* sg = s + gl * FSTR;
    float2 v[16];
    #pragma unroll
    for (int q = 0; q < 16; ++q) v[q] = sg[SIDX(t + 64*q)];
    __syncthreads();
    fft1024_64t(sg, t, v);

    const bool valid = (gl < cnt);
    const int r = t >> 2, n0 = t & 3;
    const int kbase = r + 256 * kkmap(n0);
    float* sf = (float*)sg;                 // reuse FFT region as float[SIDX(1024)]

    float lmin = 3.4e38f, lmax = 0.f;
    if (valid){
        #pragma unroll
        for (int m = 0; m < 16; ++m){
            int rr = kbase + 16*m;
            int sr = (rr + 512) & 1023;
            float m2 = fmaf(v[m].x, v[m].x, v[m].y * v[m].y);
            float val = log1pf(sqrtf(m2));
            sf[SIDX(sr)] = val;
            lmin = fminf(lmin, val);
            lmax = fmaxf(lmax, val);
        }
    }
    #pragma unroll
    for (int off = 16; off; off >>= 1){
        lmin = fminf(lmin, __shfl_xor_sync(0xFFFFFFFFu, lmin, off));
        lmax = fmaxf(lmax, __shfl_xor_sync(0xFFFFFFFFu, lmax, off));
    }
    const int wid = threadIdx.x >> 5, lane = threadIdx.x & 31;
    if (lane == 0){ smin[wid] = lmin; smax[wid] = lmax; }
    __syncthreads();
    if (threadIdx.x == 0){
        #pragma unroll
        for (int i = 1; i < 8; ++i){ lmin = fminf(lmin, smin[i]); lmax = fmaxf(lmax, smax[i]); }
        int b = img / 3;
        atomicMin(&d_gmin[b], __float_as_uint(lmin));
        atomicMax(&d_gmax[b], __float_as_uint(lmax));
    }

    // sr-direction resize for 4 columns + their mirrors (8 x 224 outputs)
    for (int i = threadIdx.x; i < 8 * OUT_HW; i += 256){
        const int cc  = i / OUT_HW;         // 0..7
        const int oy  = i - cc * OUT_HW;
        const int g   = cc & 3;
        const int mir = cc >> 2;
        if (g >= cnt) continue;
        const float* arr = (const float*)(s + g * FSTR);
        const int j0 = d_j0[oy];
        float acc = 0.f;
        #pragma unroll
        for (int k = 0; k < NTAPS; ++k){
            int j  = min(j0 + k, 1023);
            int jj = mir ? ((1024 - j) & 1023) : j;
            acc = fmaf(d_wt[oy*NTAPS + k], arr[SIDX(jj)], acc);
        }
        const int c   = c0 + g;
        const int scX = mir ? ((1536 - c) & 1023) : ((c + 512) & 1023);
        d_tmpA[((size_t)img * NN + scX) * OUT_HW + oy] = acc;
    }
}

// ---------------- pass 3: resize along sc -> ox, + normalize ----------------
__global__ void __launch_bounds__(224) resize_passB(float* __restrict__ out){
    const int bid = blockIdx.x;
    const int img = bid / OUT_HW;
    const int ox  = bid % OUT_HW;
    const int oy  = threadIdx.x;
    const int j0  = d_j0[ox];
    float acc = 0.f;
    #pragma unroll
    for (int k = 0; k < NTAPS; ++k){
        int j = min(j0 + k, 1023);
        acc = fmaf(d_wt[ox*NTAPS + k], d_tmpA[((size_t)img * NN + j) * OUT_HW + oy], acc);
    }
    const int b = img / 3;
    const float mn = __uint_as_float(d_gmin[b]);
    const float mx = __uint_as_float(d_gmax[b]);
    const float inv = 1.f / (mx - mn + 1e-8f);
    out[((size_t)img * OUT_HW + oy) * OUT_HW + ox] = (acc - mn) * inv;
}

// ---------------- launch -----------------------------------------------------
extern "C" void kernel_launch(void* const* d_in, const int* in_sizes, int n_in,
                              void* d_out, int out_size){
    (void)in_sizes; (void)n_in; (void)out_size;
    const float* images = (const float*)d_in[0];
    float* out = (float*)d_out;

    init_kernel<<<6, 256>>>();
    fft_rows_pair<<<NIMG * 128, 256>>>(images);
    fft_cols_fused<<<NIMG * 129, 256>>>();
    resize_passB<<<NIMG * OUT_HW, 224>>>(out);
}